// round 2
// baseline (speedup 1.0000x reference)
#include <cuda_runtime.h>
#include <math.h>
#include <stdint.h>

// Problem constants (dataset-fixed); runtime dims derived from in_sizes where cheap.
#define H   512     // H_ENC
#define D   256     // H_DEC (embedding)
#define XD  1280    // X = [emb(256) | attended(512) | h(512)]
#define G4  2048    // 4*H gates
#define MAXN 16384
#define MAXB 128
#define MAXV 8192

// ---------------- device scratch (static globals: no runtime allocation) ----------------
__device__ float g_P[MAXN * H];       // node projection  W_att[:,512:] @ nh   (step-invariant)
__device__ float g_Qp[MAXB * H];      // per-tree query projection + b_att
__device__ float g_score[MAXN];
__device__ float g_attw[MAXN];
__device__ float g_X[MAXB * XD];      // LSTM GEMM input rows
__device__ float g_gates[MAXB * G4];
__device__ float g_h[MAXB * H];
__device__ float g_c[MAXB * H];
__device__ int   g_cur[MAXB];
__device__ int   g_seg[MAXN];
__device__ float g_Wg[G4 * XD];       // [W_ih | W_hh] concatenated, row-major [2048,1280]
__device__ float g_bg[G4];            // b_ih + b_hh

// ---------------- packed fp32 FMA (sm_100a: 2x FFMA throughput) ----------------
__device__ __forceinline__ float2 ffma2(float2 a, float2 b, float2 c) {
    float2 d;
    asm("fma.rn.f32x2 %0, %1, %2, %3;"
        : "=l"(*reinterpret_cast<unsigned long long*>(&d))
        : "l"(*reinterpret_cast<unsigned long long*>(&a)),
          "l"(*reinterpret_cast<unsigned long long*>(&b)),
          "l"(*reinterpret_cast<unsigned long long*>(&c)));
    return d;
}

__device__ __forceinline__ float sigm(float x) { return 1.0f / (1.0f + expf(-x)); }

// ---------------- generic SGEMM:  C[M,N] (+)= A[M,K] @ B[N,K]^T (+ bias) ----------------
// 64x64 tile, 256 threads, 4x4 microtile with f32x2 accumulation.
// blockIdx.x -> N tile, blockIdx.y -> M tile, blockIdx.z -> K split slice.
// M, N multiples of 64; (K / gridDim.z) multiple of 16.
template<bool ATOMIC, bool BIAS>
__global__ void __launch_bounds__(256) gemm_tn(
    const float* __restrict__ A, int lda,
    const float* __restrict__ B, int ldb,
    float* __restrict__ C, int ldc,
    const float* __restrict__ bias, int K)
{
    __shared__ float As[16][68];
    __shared__ float Bs[16][68];

    const int tid  = threadIdx.x;
    const int m0   = blockIdx.y * 64;
    const int n0   = blockIdx.x * 64;
    const int kLen = K / gridDim.z;
    const int kBeg = blockIdx.z * kLen;

    const int lm = tid >> 2;           // 0..63 row within tile
    const int lk = (tid & 3) << 2;     // 0,4,8,12

    const float* Ap = A + (size_t)(m0 + lm) * lda + kBeg + lk;
    const float* Bp = B + (size_t)(n0 + lm) * ldb + kBeg + lk;

    const int tn = tid & 15;           // 0..15 (n micro)
    const int tm = tid >> 4;           // 0..15 (m micro)

    float2 acc[4][2];
#pragma unroll
    for (int i = 0; i < 4; i++) { acc[i][0] = make_float2(0.f, 0.f); acc[i][1] = make_float2(0.f, 0.f); }

    const int nT = kLen >> 4;
    float4 ar = *(const float4*)Ap;
    float4 br = *(const float4*)Bp;

    for (int t = 0; t < nT; t++) {
        As[lk + 0][lm] = ar.x; As[lk + 1][lm] = ar.y; As[lk + 2][lm] = ar.z; As[lk + 3][lm] = ar.w;
        Bs[lk + 0][lm] = br.x; Bs[lk + 1][lm] = br.y; Bs[lk + 2][lm] = br.z; Bs[lk + 3][lm] = br.w;
        __syncthreads();

        float4 ar2, br2;
        if (t + 1 < nT) {
            ar2 = *(const float4*)(Ap + (t + 1) * 16);
            br2 = *(const float4*)(Bp + (t + 1) * 16);
        }

#pragma unroll
        for (int k = 0; k < 16; k++) {
            float4 av = *(const float4*)&As[k][tm << 2];
            float4 bv = *(const float4*)&Bs[k][tn << 2];
            float2 b0 = make_float2(bv.x, bv.y);
            float2 b1 = make_float2(bv.z, bv.w);
            acc[0][0] = ffma2(make_float2(av.x, av.x), b0, acc[0][0]);
            acc[0][1] = ffma2(make_float2(av.x, av.x), b1, acc[0][1]);
            acc[1][0] = ffma2(make_float2(av.y, av.y), b0, acc[1][0]);
            acc[1][1] = ffma2(make_float2(av.y, av.y), b1, acc[1][1]);
            acc[2][0] = ffma2(make_float2(av.z, av.z), b0, acc[2][0]);
            acc[2][1] = ffma2(make_float2(av.z, av.z), b1, acc[2][1]);
            acc[3][0] = ffma2(make_float2(av.w, av.w), b0, acc[3][0]);
            acc[3][1] = ffma2(make_float2(av.w, av.w), b1, acc[3][1]);
        }
        __syncthreads();
        ar = ar2; br = br2;
    }

    const int cm = m0 + (tm << 2);
    const int cn = n0 + (tn << 2);
#pragma unroll
    for (int i = 0; i < 4; i++) {
        float* Cp = C + (size_t)(cm + i) * ldc + cn;
        if (ATOMIC) {
            atomicAdd(Cp + 0, acc[i][0].x);
            atomicAdd(Cp + 1, acc[i][0].y);
            atomicAdd(Cp + 2, acc[i][1].x);
            atomicAdd(Cp + 3, acc[i][1].y);
        } else {
            float4 v = make_float4(acc[i][0].x, acc[i][0].y, acc[i][1].x, acc[i][1].y);
            if (BIAS) { v.x += bias[cn]; v.y += bias[cn + 1]; v.z += bias[cn + 2]; v.w += bias[cn + 3]; }
            *(float4*)Cp = v;
        }
    }
}

// ---------------- one-time setup kernels ----------------
__global__ void seg_kernel(const int* __restrict__ roots, int Bn, int Nn) {
    int n = blockIdx.x * 256 + threadIdx.x;
    if (n >= Nn) return;
    int lo = 0, hi = Bn - 1, ans = 0;
    while (lo <= hi) {
        int mid = (lo + hi) >> 1;
        if (roots[mid] <= n) { ans = mid; lo = mid + 1; } else hi = mid - 1;
    }
    g_seg[n] = ans;
}

__global__ void init_kernel(float* __restrict__ out0, const float* __restrict__ nhs,
                            const int* __restrict__ labels, const int* __restrict__ roots,
                            const float* __restrict__ b_att, int Bn, int V) {
    int stride = gridDim.x * blockDim.x;
    int gtid = blockIdx.x * blockDim.x + threadIdx.x;
    size_t tot = (size_t)Bn * V;
    for (size_t i = gtid; i < tot; i += stride) out0[i] = 0.f;                 // outputs[0] = zeros
    for (int i = gtid; i < Bn * H; i += stride) {
        int b = i / H;
        g_h[i] = nhs[(size_t)roots[b] * H + (i % H)];                          // h0 = nh[roots]
        g_c[i] = 0.f;
        g_Qp[i] = b_att[i % H];                                                // bias prefill for split-K Qp
    }
    for (int i = gtid; i < Bn; i += stride) g_cur[i] = labels[i];              // labels[0, :]
}

__global__ void build_wg(const float* __restrict__ W_ih, const float* __restrict__ W_hh,
                         const float* __restrict__ b_ih, const float* __restrict__ b_hh) {
    int stride = gridDim.x * blockDim.x;
    int gtid = blockIdx.x * blockDim.x + threadIdx.x;
    for (int i = gtid; i < G4 * XD; i += stride) {
        int r = i / XD, k = i % XD;
        g_Wg[i] = (k < D + H) ? W_ih[r * (D + H) + k] : W_hh[r * H + (k - D - H)];
    }
    for (int i = gtid; i < G4; i += stride) g_bg[i] = b_ih[i] + b_hh[i];
}

// ---------------- per-step kernels ----------------
// score[n] = sum_j v[j] * tanh(Qp[seg[n]][j] + P[n][j])      (b_att folded into Qp)
__global__ void __launch_bounds__(256) score_kernel(const float* __restrict__ v_att, int Nn) {
    __shared__ float vs[H];
    int tid = threadIdx.x;
    for (int i = tid; i < H; i += 256) vs[i] = v_att[i];
    __syncthreads();
    int warp = tid >> 5, lane = tid & 31;
    int n = blockIdx.x * 8 + warp;
    if (n >= Nn) return;
    int b = g_seg[n];
    const float4* Pr = (const float4*)(g_P + (size_t)n * H);
    const float4* Qr = (const float4*)(g_Qp + (size_t)b * H);
    float s = 0.f;
#pragma unroll
    for (int t = 0; t < 4; t++) {
        int idx = lane + t * 32;                 // float4 index 0..127
        float4 p = Pr[idx];
        float4 q = Qr[idx];
        float4 vv = *(const float4*)&vs[idx * 4];
        s += vv.x * tanhf(p.x + q.x) + vv.y * tanhf(p.y + q.y)
           + vv.z * tanhf(p.z + q.z) + vv.w * tanhf(p.w + q.w);
    }
#pragma unroll
    for (int o = 16; o > 0; o >>= 1) s += __shfl_xor_sync(0xFFFFFFFFu, s, o);
    if (lane == 0) g_score[n] = s;
}

// Per-tree: segment softmax, attended vector, build X=[emb|att|h], prefill gates bias.
__global__ void __launch_bounds__(256) attend_kernel(
    const float* __restrict__ nhs, const int* __restrict__ roots,
    const float* __restrict__ emb_table, int Nn, int Bn) {
    int b = blockIdx.x, tid = threadIdx.x;
    int start = roots[b];
    int end = (b + 1 < Bn) ? roots[b + 1] : Nn;

    __shared__ float red[256];
    __shared__ float wbuf[256];

    // segment max
    float m = -3.4e38f;
    for (int i = start + tid; i < end; i += 256) m = fmaxf(m, g_score[i]);
    red[tid] = m; __syncthreads();
    for (int s = 128; s > 0; s >>= 1) { if (tid < s) red[tid] = fmaxf(red[tid], red[tid + s]); __syncthreads(); }
    m = red[0]; __syncthreads();

    // exp + sum
    float z = 0.f;
    for (int i = start + tid; i < end; i += 256) {
        float e = expf(g_score[i] - m);
        g_attw[i] = e;
        z += e;
    }
    red[tid] = z; __syncthreads();
    for (int s = 128; s > 0; s >>= 1) { if (tid < s) red[tid] += red[tid + s]; __syncthreads(); }
    float zinv = 1.0f / red[0];

    // attended = sum_n w[n]/Z * nh[n]   (thread owns columns tid and tid+256)
    float a0 = 0.f, a1 = 0.f;
    for (int c = start; c < end; c += 256) {
        int cnt = min(256, end - c);
        __syncthreads();
        if (tid < cnt) wbuf[tid] = g_attw[c + tid];
        __syncthreads();
#pragma unroll 4
        for (int i = 0; i < cnt; i++) {
            float w = wbuf[i];
            const float* row = nhs + (size_t)(c + i) * H;
            a0 += w * row[tid];
            a1 += w * row[tid + 256];
        }
    }

    float* X = g_X + (size_t)b * XD;
    X[D + tid]       = a0 * zinv;          // attended[0..255]
    X[D + 256 + tid] = a1 * zinv;          // attended[256..511]

    int cu = g_cur[b];
    X[tid] = emb_table[(size_t)cu * D + tid];          // emb (tid < 256 == D)
    X[D + H + tid]       = g_h[b * H + tid];           // h copy
    X[D + H + 256 + tid] = g_h[b * H + 256 + tid];

    // bias prefill for split-K gates GEMM
    for (int r = tid; r < G4; r += 256) g_gates[b * G4 + r] = g_bg[r];
}

__global__ void lstm_kernel(int Bn) {
    int idx = blockIdx.x * 256 + threadIdx.x;
    if (idx >= Bn * H) return;
    int b = idx / H, j = idx % H;
    const float* gr = g_gates + (size_t)b * G4;
    float ig = gr[j];
    float fg = gr[H + j];
    float gg = gr[2 * H + j];
    float og = gr[3 * H + j];
    float c = sigm(fg) * g_c[idx] + sigm(ig) * tanhf(gg);
    g_c[idx] = c;
    g_h[idx] = sigm(og) * tanhf(c);
}

// argmax over logits row (first-occurrence ties) + Qp bias prefill for next step.
__global__ void __launch_bounds__(256) argmax_kernel(const float* __restrict__ logits, int V,
                                                     const float* __restrict__ b_att) {
    int b = blockIdx.x, tid = threadIdx.x;
    const float* row = logits + (size_t)b * V;
    float best = -3.4e38f; int bi = 0;
    for (int j = tid; j < V; j += 256) {
        float x = row[j];
        if (x > best) { best = x; bi = j; }
    }
    __shared__ float rv[256];
    __shared__ int   ri[256];
    rv[tid] = best; ri[tid] = bi; __syncthreads();
    for (int s = 128; s > 0; s >>= 1) {
        if (tid < s) {
            if (rv[tid + s] > rv[tid] || (rv[tid + s] == rv[tid] && ri[tid + s] < ri[tid])) {
                rv[tid] = rv[tid + s]; ri[tid] = ri[tid + s];
            }
        }
        __syncthreads();
    }
    if (tid == 0) g_cur[b] = ri[0];
    // prefill Qp with b_att for next step's split-K atomic GEMM
    for (int j = tid; j < H; j += 256) g_Qp[b * H + j] = b_att[j];
}

// ---------------- host ----------------
extern "C" void kernel_launch(void* const* d_in, const int* in_sizes, int n_in,
                              void* d_out, int out_size) {
    const float* nhs    = (const float*)d_in[0];
    const int*   labels = (const int*)  d_in[1];
    const int*   roots  = (const int*)  d_in[2];
    const float* emb    = (const float*)d_in[3];
    const float* W_att  = (const float*)d_in[4];
    const float* b_att  = (const float*)d_in[5];
    const float* v_att  = (const float*)d_in[6];
    const float* W_ih   = (const float*)d_in[7];
    const float* W_hh   = (const float*)d_in[8];
    const float* b_ih   = (const float*)d_in[9];
    const float* b_hh   = (const float*)d_in[10];
    const float* W_out  = (const float*)d_in[11];
    const float* b_out  = (const float*)d_in[12];
    float* out = (float*)d_out;

    const int Nn = in_sizes[0] / H;
    const int Bn = in_sizes[2];
    const int L  = in_sizes[1] / Bn;
    const int V  = in_sizes[12];
    const int steps = L - 1;

    float *pP, *pQp, *pX, *pG, *pH;
    cudaGetSymbolAddress((void**)&pP,  g_P);
    cudaGetSymbolAddress((void**)&pQp, g_Qp);
    cudaGetSymbolAddress((void**)&pX,  g_X);
    cudaGetSymbolAddress((void**)&pG,  g_gates);
    cudaGetSymbolAddress((void**)&pH,  g_h);
    float* pWg;
    cudaGetSymbolAddress((void**)&pWg, g_Wg);

    // ---- one-time precompute ----
    seg_kernel<<<(Nn + 255) / 256, 256>>>(roots, Bn, Nn);
    init_kernel<<<1024, 256>>>(out, nhs, labels, roots, b_att, Bn, V);
    build_wg<<<2048, 256>>>(W_ih, W_hh, b_ih, b_hh);

    // P = nh @ W_att[:,512:]^T     [Nn,512] x [512,512]
    {
        dim3 g(H / 64, Nn / 64, 1);
        gemm_tn<false, false><<<g, 256>>>(nhs, H, W_att + H, 2 * H, pP, H, nullptr, H);
    }

    // ---- decoder steps ----
    for (int t = 0; t < steps; t++) {
        // Qp = h @ W_att[:,:512]^T + b_att     (split-K=4, atomic, bias prefilled)
        {
            dim3 g(H / 64, Bn / 64, 4);
            gemm_tn<true, false><<<g, 256>>>(pH, H, W_att, 2 * H, pQp, H, nullptr, H);
        }
        // scores
        score_kernel<<<(Nn + 7) / 8, 256>>>(v_att, Nn);
        // softmax + attended + X build + gates bias prefill
        attend_kernel<<<Bn, 256>>>(nhs, roots, emb, Nn, Bn);
        // gates = X @ Wg^T + (b_ih+b_hh)       (split-K=4, atomic, bias prefilled)
        {
            dim3 g(G4 / 64, Bn / 64, 4);
            gemm_tn<true, false><<<g, 256>>>(pX, XD, pWg, XD, pG, G4, nullptr, XD);
        }
        // LSTM cell pointwise
        lstm_kernel<<<(Bn * H + 255) / 256, 256>>>(Bn);
        // logits = h @ W_out^T + b_out  -> d_out slab (t+1)
        float* slab = out + (size_t)(t + 1) * Bn * V;
        {
            dim3 g(V / 64, Bn / 64, 1);
            gemm_tn<false, true><<<g, 256>>>(pH, H, W_out, H, slab, V, b_out, H);
        }
        // feedback argmax (+ Qp bias prefill for next step)
        argmax_kernel<<<Bn, 256>>>(slab, V, b_att);
    }
}